// round 3
// baseline (speedup 1.0000x reference)
#include <cuda_runtime.h>

#define B_ 256
#define T_ 512
#define D_ 128
#define U_ 128
#define C_ 64
#define M_ (B_*T_)   // 131072 rows

__device__ float g_H[(size_t)M_ * U_];   // tanh(X@W1+b1)
__device__ float g_F[(size_t)M_ * U_];   // recurrence features

typedef unsigned long long ull;

__device__ __forceinline__ ull pk2(float x, float y) {
    ull r; asm("mov.b64 %0, {%1,%2};" : "=l"(r) : "f"(x), "f"(y)); return r;
}
__device__ __forceinline__ void upk2(ull v, float& x, float& y) {
    asm("mov.b64 {%0,%1}, %2;" : "=f"(x), "=f"(y) : "l"(v));
}
__device__ __forceinline__ ull ffma2(ull a, ull b, ull c) {
    ull d; asm("fma.rn.f32x2 %0, %1, %2, %3;" : "=l"(d) : "l"(a), "l"(b), "l"(c)); return d;
}
__device__ __forceinline__ float tanh_fast(float x) {
    float y; asm("tanh.approx.f32 %0, %1;" : "=f"(y) : "f"(x)); return y;
}
__device__ __forceinline__ float ldcs(const float* p) {
    float v; asm("ld.global.cs.f32 %0, [%1];" : "=f"(v) : "l"(p)); return v;
}
__device__ __forceinline__ void stcs(float* p, float v) {
    asm("st.global.cs.f32 [%0], %1;" :: "l"(p), "f"(v) : "memory");
}

// ---------------------------------------------------------------------------
// K1: H = tanh(X @ W1 + b1). 64 rows x 128 cols per CTA, 256 thr, micro 8x4.
// W1 staged in TWO k-halves (32KB buffer) + X tile (32KB) = 64KB -> 3 CTAs/SM.
// ---------------------------------------------------------------------------
__global__ void __launch_bounds__(256, 3)
k1_in_gemm(const float* __restrict__ X, const float* __restrict__ W1,
           const float* __restrict__ b1)
{
    extern __shared__ float smem[];
    float2* Wp = (float2*)smem;            // [32][128] float2  (32 KB)
    float*  Xs = smem + 8192;              // [64][128] float   (32 KB)
    const int tid = threadIdx.x;
    const int m0 = blockIdx.x * 64;

    // stage X tile (once)
    {
        const int q  = (tid & 31) * 4;
        const int r0 = tid >> 5;
        #pragma unroll
        for (int pass = 0; pass < 8; pass++) {
            int row = r0 + pass * 8;
            float4 v;
            const float* src = X + (size_t)(m0+row)*128 + q;
            v.x = ldcs(src+0); v.y = ldcs(src+1); v.z = ldcs(src+2); v.w = ldcs(src+3);
            *(float4*)(Xs + row*128 + q) = v;
        }
    }

    const int tc = tid & 31;   // cols 4tc..4tc+3
    const int tr = tid >> 5;   // rows 8tr..8tr+7 (warp-uniform -> broadcast x)
    ull acc[8][4];
    #pragma unroll
    for (int i = 0; i < 8; i++)
        #pragma unroll
        for (int c = 0; c < 4; c++) acc[i][c] = 0ULL;

    const float2* wbase = Wp + tc * 4;

    #pragma unroll
    for (int half = 0; half < 2; half++) {
        // stage 32 k-pairs of W1 (k rows half*64 .. half*64+63), pair-interleaved
        {
            const int c4  = (tid & 31) * 4;
            const int kp0 = tid >> 5;
            #pragma unroll
            for (int pass = 0; pass < 4; pass++) {
                int kp = kp0 + pass * 8;
                int k  = half*64 + 2*kp;
                float4 a = *(const float4*)(W1 + (size_t)k     * 128 + c4);
                float4 b = *(const float4*)(W1 + (size_t)(k+1) * 128 + c4);
                float2* w = Wp + kp*128 + c4;
                w[0] = make_float2(a.x, b.x);
                w[1] = make_float2(a.y, b.y);
                w[2] = make_float2(a.z, b.z);
                w[3] = make_float2(a.w, b.w);
            }
        }
        __syncthreads();

        const float* xbase = Xs + tr * 8 * 128 + half * 64;
        #pragma unroll 8
        for (int kp = 0; kp < 32; kp++) {
            ulonglong2 wv0 = *(const ulonglong2*)(wbase + (size_t)kp*128);
            ulonglong2 wv1 = *(const ulonglong2*)(wbase + (size_t)kp*128 + 2);
            #pragma unroll
            for (int i = 0; i < 8; i++) {
                ull xp = *(const ull*)(xbase + i*128 + 2*kp);
                acc[i][0] = ffma2(xp, wv0.x, acc[i][0]);
                acc[i][1] = ffma2(xp, wv0.y, acc[i][1]);
                acc[i][2] = ffma2(xp, wv1.x, acc[i][2]);
                acc[i][3] = ffma2(xp, wv1.y, acc[i][3]);
            }
        }
        __syncthreads();   // all warps done with this W half before restage
    }

    float bb[4];
    #pragma unroll
    for (int c = 0; c < 4; c++) bb[c] = __ldg(b1 + tc*4 + c);

    #pragma unroll
    for (int i = 0; i < 8; i++) {
        int row = m0 + tr*8 + i;
        float4 o; float x, y;
        upk2(acc[i][0], x, y); o.x = tanh_fast(x + y + bb[0]);
        upk2(acc[i][1], x, y); o.y = tanh_fast(x + y + bb[1]);
        upk2(acc[i][2], x, y); o.z = tanh_fast(x + y + bb[2]);
        upk2(acc[i][3], x, y); o.w = tanh_fast(x + y + bb[3]);
        *(float4*)(g_H + (size_t)row*128 + tc*4) = o;
    }
}

// ---------------------------------------------------------------------------
// K2: recurrence. 128 CTAs x 256 threads; two chains per CTA (one per half).
// W2[:,j] in registers (64 f32x2). State in smem double-buffered, per-chain
// named barrier. H prefetched 4 steps ahead (register ring, loop unrolled x4)
// with streaming loads; F written with .cs (evict-first) to keep H in L2.
// ---------------------------------------------------------------------------
__global__ void __launch_bounds__(256)
k2_recurrence(const float* __restrict__ W2, const float* __restrict__ b2)
{
    __shared__ __align__(16) float st[2][2][128];   // [chain][buf][u]
    const int tid   = threadIdx.x;
    const int chain = tid >> 7;
    const int j     = tid & 127;
    const int b     = blockIdx.x * 2 + chain;

    ull w[64];
    #pragma unroll
    for (int p = 0; p < 64; p++)
        w[p] = pk2(__ldg(W2 + (size_t)(2*p)*128 + j),
                   __ldg(W2 + (size_t)(2*p+1)*128 + j));
    const float b2v = __ldg(b2 + j);

    st[chain][0][j] = 0.0f;
    __syncthreads();

    const float* Hp = g_H + (size_t)b * (T_*128) + j;
    float*       Fp = g_F + (size_t)b * (T_*128) + j;

    // prefetch ring: h[0..3]
    float h0 = ldcs(Hp + 0*128);
    float h1 = ldcs(Hp + 1*128);
    float h2 = ldcs(Hp + 2*128);
    float h3 = ldcs(Hp + 3*128);

    int buf = 0;
    #pragma unroll 1
    for (int t = 0; t < T_; t += 4) {
        #pragma unroll
        for (int u = 0; u < 4; u++) {
            float hv = (u == 0) ? h0 : (u == 1) ? h1 : (u == 2) ? h2 : h3;
            // refill slot with step t+u+4
            int tp = t + u + 4;
            float hn = 0.0f;
            if (tp < T_) hn = ldcs(Hp + (size_t)tp*128);
            if (u == 0) h0 = hn; else if (u == 1) h1 = hn;
            else if (u == 2) h2 = hn; else h3 = hn;

            const ulonglong2* sp = (const ulonglong2*)st[chain][buf];
            ull a0 = 0ULL, a1 = 0ULL, a2 = 0ULL, a3 = 0ULL;
            #pragma unroll
            for (int q = 0; q < 32; q += 2) {
                ulonglong2 s01 = sp[q];
                ulonglong2 s23 = sp[q+1];
                a0 = ffma2(s01.x, w[2*q+0], a0);
                a1 = ffma2(s01.y, w[2*q+1], a1);
                a2 = ffma2(s23.x, w[2*q+2], a2);
                a3 = ffma2(s23.y, w[2*q+3], a3);
            }
            float x0,y0,x1,y1,x2,y2,x3,y3;
            upk2(a0,x0,y0); upk2(a1,x1,y1); upk2(a2,x2,y2); upk2(a3,x3,y3);
            float s = ((x0+y0)+(x1+y1)) + ((x2+y2)+(x3+y3)) + b2v;

            float yv = hv + tanh_fast(s);
            st[chain][buf^1][j] = yv;
            stcs(Fp + (size_t)(t+u)*128, yv);
            asm volatile("bar.sync %0, 128;" :: "r"(chain + 1) : "memory");
            buf ^= 1;
        }
    }
}

// ---------------------------------------------------------------------------
// K3: OUT = F @ Wc + bc. Tile 128 rows x 64 cols, 256 thr, micro 8x4.
// ---------------------------------------------------------------------------
__global__ void __launch_bounds__(256, 2)
k3_head(const float* __restrict__ Wc, const float* __restrict__ bc,
        float* __restrict__ out)
{
    extern __shared__ float smem[];
    float2* Wp = (float2*)smem;        // [64][64] float2  (32 KB)
    float*  Xs = smem + 8192;          // [128][128] float (64 KB)
    const int tid = threadIdx.x;
    const int m0 = blockIdx.x * 128;

    {
        const int c4  = (tid & 15) * 4;
        const int kp0 = tid >> 4;      // 0..15
        #pragma unroll
        for (int pass = 0; pass < 4; pass++) {
            int kp = kp0 + pass * 16;
            float4 a = *(const float4*)(Wc + (size_t)(2*kp)   * 64 + c4);
            float4 b = *(const float4*)(Wc + (size_t)(2*kp+1) * 64 + c4);
            float2* w = Wp + kp*64 + c4;
            w[0] = make_float2(a.x, b.x);
            w[1] = make_float2(a.y, b.y);
            w[2] = make_float2(a.z, b.z);
            w[3] = make_float2(a.w, b.w);
        }
    }
    {
        const int q  = (tid & 31) * 4;
        const int r0 = tid >> 5;
        #pragma unroll
        for (int pass = 0; pass < 16; pass++) {
            int row = r0 + pass * 8;
            const float* src = g_F + (size_t)(m0+row)*128 + q;
            float4 v;
            v.x = ldcs(src+0); v.y = ldcs(src+1); v.z = ldcs(src+2); v.w = ldcs(src+3);
            *(float4*)(Xs + row*128 + q) = v;
        }
    }
    __syncthreads();

    const int tc = tid & 15;   // cols 4tc..4tc+3
    const int tr = tid >> 4;   // rows 8tr..8tr+7
    ull acc[8][4];
    #pragma unroll
    for (int i = 0; i < 8; i++)
        #pragma unroll
        for (int c = 0; c < 4; c++) acc[i][c] = 0ULL;

    const float*  xbase = Xs + tr * 8 * 128;
    const float2* wbase = Wp + tc * 4;

    #pragma unroll 8
    for (int kp = 0; kp < 64; kp++) {
        ulonglong2 wv0 = *(const ulonglong2*)(wbase + (size_t)kp*64);
        ulonglong2 wv1 = *(const ulonglong2*)(wbase + (size_t)kp*64 + 2);
        #pragma unroll
        for (int i = 0; i < 8; i++) {
            ull xp = *(const ull*)(xbase + i*128 + 2*kp);
            acc[i][0] = ffma2(xp, wv0.x, acc[i][0]);
            acc[i][1] = ffma2(xp, wv0.y, acc[i][1]);
            acc[i][2] = ffma2(xp, wv1.x, acc[i][2]);
            acc[i][3] = ffma2(xp, wv1.y, acc[i][3]);
        }
    }

    float bb[4];
    #pragma unroll
    for (int c = 0; c < 4; c++) bb[c] = __ldg(bc + tc*4 + c);

    #pragma unroll
    for (int i = 0; i < 8; i++) {
        int row = m0 + tr*8 + i;
        float4 o; float x, y;
        upk2(acc[i][0], x, y); o.x = x + y + bb[0];
        upk2(acc[i][1], x, y); o.y = x + y + bb[1];
        upk2(acc[i][2], x, y); o.z = x + y + bb[2];
        upk2(acc[i][3], x, y); o.w = x + y + bb[3];
        *(float4*)(out + (size_t)row*64 + tc*4) = o;
    }
}

extern "C" void kernel_launch(void* const* d_in, const int* in_sizes, int n_in,
                              void* d_out, int out_size) {
    (void)in_sizes; (void)n_in; (void)out_size;
    const float* X  = (const float*)d_in[0];
    const float* W1 = (const float*)d_in[1];
    const float* b1 = (const float*)d_in[2];
    const float* W2 = (const float*)d_in[3];
    const float* b2 = (const float*)d_in[4];
    const float* Wc = (const float*)d_in[5];
    const float* bc = (const float*)d_in[6];
    float* out = (float*)d_out;

    cudaFuncSetAttribute(k1_in_gemm, cudaFuncAttributeMaxDynamicSharedMemorySize, 65536);
    cudaFuncSetAttribute(k3_head,    cudaFuncAttributeMaxDynamicSharedMemorySize, 98304);

    k1_in_gemm<<<M_/64, 256, 65536>>>(X, W1, b1);
    k2_recurrence<<<B_/2, 256>>>(W2, b2);
    k3_head<<<M_/128, 256, 98304>>>(Wc, bc, out);
}

// round 4
// speedup vs baseline: 1.2860x; 1.2860x over previous
#include <cuda_runtime.h>

#define B_ 256
#define T_ 512
#define D_ 128
#define U_ 128
#define C_ 64
#define M_ (B_*T_)   // 131072 rows

__device__ float g_H[(size_t)M_ * U_];   // tanh(X@W1+b1)
__device__ float g_F[(size_t)M_ * U_];   // recurrence features

typedef unsigned long long ull;

__device__ __forceinline__ ull pk2(float x, float y) {
    ull r; asm("mov.b64 %0, {%1,%2};" : "=l"(r) : "f"(x), "f"(y)); return r;
}
__device__ __forceinline__ void upk2(ull v, float& x, float& y) {
    asm("mov.b64 {%0,%1}, %2;" : "=f"(x), "=f"(y) : "l"(v));
}
__device__ __forceinline__ ull ffma2(ull a, ull b, ull c) {
    ull d; asm("fma.rn.f32x2 %0, %1, %2, %3;" : "=l"(d) : "l"(a), "l"(b), "l"(c)); return d;
}
__device__ __forceinline__ float tanh_fast(float x) {
    float y; asm("tanh.approx.f32 %0, %1;" : "=f"(y) : "f"(x)); return y;
}
__device__ __forceinline__ float ldcs(const float* p) {
    float v; asm("ld.global.cs.f32 %0, [%1];" : "=f"(v) : "l"(p)); return v;
}
__device__ __forceinline__ void stcs(float* p, float v) {
    asm("st.global.cs.f32 [%0], %1;" :: "l"(p), "f"(v) : "memory");
}

// ---------------------------------------------------------------------------
// K1 (reverted to R2): H = tanh(X @ W1 + b1).
// Tile 64 rows x 128 cols, 256 thr, micro 8x4, W pair-interleaved in smem.
// ---------------------------------------------------------------------------
__global__ void __launch_bounds__(256, 2)
k1_in_gemm(const float* __restrict__ X, const float* __restrict__ W1,
           const float* __restrict__ b1)
{
    extern __shared__ float smem[];
    float2* Wp = (float2*)smem;            // [64][128] float2  (64 KB)
    float*  Xs = smem + 16384;             // [64][128] float   (32 KB)
    const int tid = threadIdx.x;
    const int m0 = blockIdx.x * 64;

    {   // stage W1 pair-interleaved over k
        const int c4 = (tid & 31) * 4;
        const int kp0 = tid >> 5;
        #pragma unroll
        for (int pass = 0; pass < 8; pass++) {
            int kp = kp0 + pass * 8;
            float4 a = *(const float4*)(W1 + (size_t)(2*kp)   * 128 + c4);
            float4 b = *(const float4*)(W1 + (size_t)(2*kp+1) * 128 + c4);
            float2* w = Wp + kp*128 + c4;
            w[0] = make_float2(a.x, b.x);
            w[1] = make_float2(a.y, b.y);
            w[2] = make_float2(a.z, b.z);
            w[3] = make_float2(a.w, b.w);
        }
    }
    {   // stage X tile row-major (vector loads)
        const int q  = (tid & 31) * 4;
        const int r0 = tid >> 5;
        #pragma unroll
        for (int pass = 0; pass < 8; pass++) {
            int row = r0 + pass * 8;
            *(float4*)(Xs + row*128 + q) =
                *(const float4*)(X + (size_t)(m0+row)*128 + q);
        }
    }
    __syncthreads();

    const int tc = tid & 31;
    const int tr = tid >> 5;
    ull acc[8][4];
    #pragma unroll
    for (int i = 0; i < 8; i++)
        #pragma unroll
        for (int c = 0; c < 4; c++) acc[i][c] = 0ULL;

    const float*  xbase = Xs + tr * 8 * 128;
    const float2* wbase = Wp + tc * 4;

    #pragma unroll 8
    for (int kp = 0; kp < 64; kp++) {
        ulonglong2 wv0 = *(const ulonglong2*)(wbase + (size_t)kp*128);
        ulonglong2 wv1 = *(const ulonglong2*)(wbase + (size_t)kp*128 + 2);
        #pragma unroll
        for (int i = 0; i < 8; i++) {
            ull xp = *(const ull*)(xbase + i*128 + 2*kp);
            acc[i][0] = ffma2(xp, wv0.x, acc[i][0]);
            acc[i][1] = ffma2(xp, wv0.y, acc[i][1]);
            acc[i][2] = ffma2(xp, wv1.x, acc[i][2]);
            acc[i][3] = ffma2(xp, wv1.y, acc[i][3]);
        }
    }

    float bb[4];
    #pragma unroll
    for (int c = 0; c < 4; c++) bb[c] = __ldg(b1 + tc*4 + c);

    #pragma unroll
    for (int i = 0; i < 8; i++) {
        int row = m0 + tr*8 + i;
        float4 o; float x, y;
        upk2(acc[i][0], x, y); o.x = tanh_fast(x + y + bb[0]);
        upk2(acc[i][1], x, y); o.y = tanh_fast(x + y + bb[1]);
        upk2(acc[i][2], x, y); o.z = tanh_fast(x + y + bb[2]);
        upk2(acc[i][3], x, y); o.w = tanh_fast(x + y + bb[3]);
        *(float4*)(g_H + (size_t)row*128 + tc*4) = o;
    }
}

// ---------------------------------------------------------------------------
// K2: recurrence, TWO chains per THREAD. 128 CTAs x 128 threads (single wave).
// Thread j holds W2[:,j] once (64 f32x2 regs) and computes both chains' dot
// products per step -> fixed per-step latency (LDS/bar/tanh) amortized 2x,
// 8 independent FFMA2 accumulator chains for ILP. One __syncthreads per step.
// H prefetch ring-2 per chain (streaming), F stored evict-first.
// ---------------------------------------------------------------------------
__global__ void __launch_bounds__(128)
k2_recurrence(const float* __restrict__ W2, const float* __restrict__ b2)
{
    __shared__ __align__(16) float st[2][2][128];   // [chain][buf][u]
    const int j  = threadIdx.x;
    const int b0 = blockIdx.x * 2;

    ull w[64];
    #pragma unroll
    for (int p = 0; p < 64; p++)
        w[p] = pk2(__ldg(W2 + (size_t)(2*p)*128 + j),
                   __ldg(W2 + (size_t)(2*p+1)*128 + j));
    const float b2v = __ldg(b2 + j);

    st[0][0][j] = 0.0f;
    st[1][0][j] = 0.0f;
    __syncthreads();

    const float* HpA = g_H + (size_t)b0     * (T_*128) + j;
    const float* HpB = g_H + (size_t)(b0+1) * (T_*128) + j;
    float*       FpA = g_F + (size_t)b0     * (T_*128) + j;
    float*       FpB = g_F + (size_t)(b0+1) * (T_*128) + j;

    // prefetch ring (2 deep per chain)
    float hA0 = ldcs(HpA);        float hA1 = ldcs(HpA + 128);
    float hB0 = ldcs(HpB);        float hB1 = ldcs(HpB + 128);

    int buf = 0;
    #pragma unroll 1
    for (int t = 0; t < T_; t += 2) {
        #pragma unroll
        for (int u = 0; u < 2; u++) {
            float hvA = u ? hA1 : hA0;
            float hvB = u ? hB1 : hB0;
            int tp = t + u + 2;
            float hnA = 0.0f, hnB = 0.0f;
            if (tp < T_) {
                hnA = ldcs(HpA + (size_t)tp*128);
                hnB = ldcs(HpB + (size_t)tp*128);
            }
            if (u) { hA1 = hnA; hB1 = hnB; } else { hA0 = hnA; hB0 = hnB; }

            const ulonglong2* spA = (const ulonglong2*)st[0][buf];
            const ulonglong2* spB = (const ulonglong2*)st[1][buf];
            ull a0=0ULL,a1=0ULL,a2=0ULL,a3=0ULL;
            ull c0=0ULL,c1=0ULL,c2=0ULL,c3=0ULL;
            #pragma unroll
            for (int q = 0; q < 32; q += 2) {
                ulonglong2 sA01 = spA[q];
                ulonglong2 sA23 = spA[q+1];
                ulonglong2 sB01 = spB[q];
                ulonglong2 sB23 = spB[q+1];
                a0 = ffma2(sA01.x, w[2*q+0], a0);
                a1 = ffma2(sA01.y, w[2*q+1], a1);
                a2 = ffma2(sA23.x, w[2*q+2], a2);
                a3 = ffma2(sA23.y, w[2*q+3], a3);
                c0 = ffma2(sB01.x, w[2*q+0], c0);
                c1 = ffma2(sB01.y, w[2*q+1], c1);
                c2 = ffma2(sB23.x, w[2*q+2], c2);
                c3 = ffma2(sB23.y, w[2*q+3], c3);
            }
            float x0,y0,x1,y1,x2,y2,x3,y3;
            upk2(a0,x0,y0); upk2(a1,x1,y1); upk2(a2,x2,y2); upk2(a3,x3,y3);
            float sA = ((x0+y0)+(x1+y1)) + ((x2+y2)+(x3+y3)) + b2v;
            upk2(c0,x0,y0); upk2(c1,x1,y1); upk2(c2,x2,y2); upk2(c3,x3,y3);
            float sB = ((x0+y0)+(x1+y1)) + ((x2+y2)+(x3+y3)) + b2v;

            float yA = hvA + tanh_fast(sA);
            float yB = hvB + tanh_fast(sB);
            st[0][buf^1][j] = yA;
            st[1][buf^1][j] = yB;
            stcs(FpA + (size_t)(t+u)*128, yA);
            stcs(FpB + (size_t)(t+u)*128, yB);
            __syncthreads();
            buf ^= 1;
        }
    }
}

// ---------------------------------------------------------------------------
// K3 (reverted to R2): OUT = F @ Wc + bc. Tile 128x64, 256 thr, micro 8x4.
// ---------------------------------------------------------------------------
__global__ void __launch_bounds__(256, 2)
k3_head(const float* __restrict__ Wc, const float* __restrict__ bc,
        float* __restrict__ out)
{
    extern __shared__ float smem[];
    float2* Wp = (float2*)smem;        // [64][64] float2  (32 KB)
    float*  Xs = smem + 8192;          // [128][128] float (64 KB)
    const int tid = threadIdx.x;
    const int m0 = blockIdx.x * 128;

    {
        const int c4  = (tid & 15) * 4;
        const int kp0 = tid >> 4;
        #pragma unroll
        for (int pass = 0; pass < 4; pass++) {
            int kp = kp0 + pass * 16;
            float4 a = *(const float4*)(Wc + (size_t)(2*kp)   * 64 + c4);
            float4 b = *(const float4*)(Wc + (size_t)(2*kp+1) * 64 + c4);
            float2* w = Wp + kp*64 + c4;
            w[0] = make_float2(a.x, b.x);
            w[1] = make_float2(a.y, b.y);
            w[2] = make_float2(a.z, b.z);
            w[3] = make_float2(a.w, b.w);
        }
    }
    {
        const int q  = (tid & 31) * 4;
        const int r0 = tid >> 5;
        #pragma unroll
        for (int pass = 0; pass < 16; pass++) {
            int row = r0 + pass * 8;
            *(float4*)(Xs + row*128 + q) =
                *(const float4*)(g_F + (size_t)(m0+row)*128 + q);
        }
    }
    __syncthreads();

    const int tc = tid & 15;
    const int tr = tid >> 4;
    ull acc[8][4];
    #pragma unroll
    for (int i = 0; i < 8; i++)
        #pragma unroll
        for (int c = 0; c < 4; c++) acc[i][c] = 0ULL;

    const float*  xbase = Xs + tr * 8 * 128;
    const float2* wbase = Wp + tc * 4;

    #pragma unroll 8
    for (int kp = 0; kp < 64; kp++) {
        ulonglong2 wv0 = *(const ulonglong2*)(wbase + (size_t)kp*64);
        ulonglong2 wv1 = *(const ulonglong2*)(wbase + (size_t)kp*64 + 2);
        #pragma unroll
        for (int i = 0; i < 8; i++) {
            ull xp = *(const ull*)(xbase + i*128 + 2*kp);
            acc[i][0] = ffma2(xp, wv0.x, acc[i][0]);
            acc[i][1] = ffma2(xp, wv0.y, acc[i][1]);
            acc[i][2] = ffma2(xp, wv1.x, acc[i][2]);
            acc[i][3] = ffma2(xp, wv1.y, acc[i][3]);
        }
    }

    float bb[4];
    #pragma unroll
    for (int c = 0; c < 4; c++) bb[c] = __ldg(bc + tc*4 + c);

    #pragma unroll
    for (int i = 0; i < 8; i++) {
        int row = m0 + tr*8 + i;
        float4 o; float x, y;
        upk2(acc[i][0], x, y); o.x = x + y + bb[0];
        upk2(acc[i][1], x, y); o.y = x + y + bb[1];
        upk2(acc[i][2], x, y); o.z = x + y + bb[2];
        upk2(acc[i][3], x, y); o.w = x + y + bb[3];
        *(float4*)(out + (size_t)row*64 + tc*4) = o;
    }
}

extern "C" void kernel_launch(void* const* d_in, const int* in_sizes, int n_in,
                              void* d_out, int out_size) {
    (void)in_sizes; (void)n_in; (void)out_size;
    const float* X  = (const float*)d_in[0];
    const float* W1 = (const float*)d_in[1];
    const float* b1 = (const float*)d_in[2];
    const float* W2 = (const float*)d_in[3];
    const float* b2 = (const float*)d_in[4];
    const float* Wc = (const float*)d_in[5];
    const float* bc = (const float*)d_in[6];
    float* out = (float*)d_out;

    cudaFuncSetAttribute(k1_in_gemm, cudaFuncAttributeMaxDynamicSharedMemorySize, 98304);
    cudaFuncSetAttribute(k3_head,    cudaFuncAttributeMaxDynamicSharedMemorySize, 98304);

    k1_in_gemm<<<M_/64, 256, 98304>>>(X, W1, b1);
    k2_recurrence<<<B_/2, 128>>>(W2, b2);
    k3_head<<<M_/128, 256, 98304>>>(Wc, bc, out);
}

// round 5
// speedup vs baseline: 1.6442x; 1.2786x over previous
#include <cuda_runtime.h>

#define B_ 256
#define T_ 512
#define D_ 128
#define U_ 128
#define C_ 64
#define M_ (B_*T_)   // 131072 rows

__device__ float g_H[(size_t)M_ * U_];   // tanh(X@W1+b1)
__device__ float g_F[(size_t)M_ * U_];   // recurrence features

typedef unsigned long long ull;

__device__ __forceinline__ ull pk2(float x, float y) {
    ull r; asm("mov.b64 %0, {%1,%2};" : "=l"(r) : "f"(x), "f"(y)); return r;
}
__device__ __forceinline__ void upk2(ull v, float& x, float& y) {
    asm("mov.b64 {%0,%1}, %2;" : "=f"(x), "=f"(y) : "l"(v));
}
__device__ __forceinline__ ull ffma2(ull a, ull b, ull c) {
    ull d; asm("fma.rn.f32x2 %0, %1, %2, %3;" : "=l"(d) : "l"(a), "l"(b), "l"(c)); return d;
}
__device__ __forceinline__ float tanh_fast(float x) {
    float y; asm("tanh.approx.f32 %0, %1;" : "=f"(y) : "f"(x)); return y;
}

// ---------------------------------------------------------------------------
// K1: H = tanh(X @ W1 + b1). Tile 64x128, 256 thr, micro 8x4 (R4 version,
// measured 107.7us). W pair-interleaved in smem, x warp-uniform broadcast.
// ---------------------------------------------------------------------------
__global__ void __launch_bounds__(256, 2)
k1_in_gemm(const float* __restrict__ X, const float* __restrict__ W1,
           const float* __restrict__ b1)
{
    extern __shared__ float smem[];
    float2* Wp = (float2*)smem;            // [64][128] float2  (64 KB)
    float*  Xs = smem + 16384;             // [64][128] float   (32 KB)
    const int tid = threadIdx.x;
    const int m0 = blockIdx.x * 64;

    {
        const int c4 = (tid & 31) * 4;
        const int kp0 = tid >> 5;
        #pragma unroll
        for (int pass = 0; pass < 8; pass++) {
            int kp = kp0 + pass * 8;
            float4 a = *(const float4*)(W1 + (size_t)(2*kp)   * 128 + c4);
            float4 b = *(const float4*)(W1 + (size_t)(2*kp+1) * 128 + c4);
            float2* w = Wp + kp*128 + c4;
            w[0] = make_float2(a.x, b.x);
            w[1] = make_float2(a.y, b.y);
            w[2] = make_float2(a.z, b.z);
            w[3] = make_float2(a.w, b.w);
        }
    }
    {
        const int q  = (tid & 31) * 4;
        const int r0 = tid >> 5;
        #pragma unroll
        for (int pass = 0; pass < 8; pass++) {
            int row = r0 + pass * 8;
            *(float4*)(Xs + row*128 + q) =
                *(const float4*)(X + (size_t)(m0+row)*128 + q);
        }
    }
    __syncthreads();

    const int tc = tid & 31;
    const int tr = tid >> 5;
    ull acc[8][4];
    #pragma unroll
    for (int i = 0; i < 8; i++)
        #pragma unroll
        for (int c = 0; c < 4; c++) acc[i][c] = 0ULL;

    const float*  xbase = Xs + tr * 8 * 128;
    const float2* wbase = Wp + tc * 4;

    #pragma unroll 8
    for (int kp = 0; kp < 64; kp++) {
        ulonglong2 wv0 = *(const ulonglong2*)(wbase + (size_t)kp*128);
        ulonglong2 wv1 = *(const ulonglong2*)(wbase + (size_t)kp*128 + 2);
        #pragma unroll
        for (int i = 0; i < 8; i++) {
            ull xp = *(const ull*)(xbase + i*128 + 2*kp);
            acc[i][0] = ffma2(xp, wv0.x, acc[i][0]);
            acc[i][1] = ffma2(xp, wv0.y, acc[i][1]);
            acc[i][2] = ffma2(xp, wv1.x, acc[i][2]);
            acc[i][3] = ffma2(xp, wv1.y, acc[i][3]);
        }
    }

    float bb[4];
    #pragma unroll
    for (int c = 0; c < 4; c++) bb[c] = __ldg(b1 + tc*4 + c);

    #pragma unroll
    for (int i = 0; i < 8; i++) {
        int row = m0 + tr*8 + i;
        float4 o; float x, y;
        upk2(acc[i][0], x, y); o.x = tanh_fast(x + y + bb[0]);
        upk2(acc[i][1], x, y); o.y = tanh_fast(x + y + bb[1]);
        upk2(acc[i][2], x, y); o.z = tanh_fast(x + y + bb[2]);
        upk2(acc[i][3], x, y); o.w = tanh_fast(x + y + bb[3]);
        *(float4*)(g_H + (size_t)row*128 + tc*4) = o;
    }
}

// ---------------------------------------------------------------------------
// K2: recurrence, K-SPLIT x2. 128 CTAs x 512 threads; 2 chains per CTA
// (chain = tid>>8). Within a chain: column j = (tid&255)>>1, half h = tid&1.
// Thread holds HALF a W2 column (32 f32x2 = 64 regs) -> 4 warps/SMSP resident
// for latency hiding without duplicating W2. Halves combined via shfl.xor(1)
// (partner = adjacent lane, same warp). State smem halves padded +16B so the
// two broadcast addresses per LDS hit distinct banks. One named bar per
// chain per step.
// ---------------------------------------------------------------------------
#define ST_PAD 4                       // 16B gap between halves
#define ST_SZ  (128 + ST_PAD + 4)      // floats per state buffer (aligned)

__global__ void __launch_bounds__(512)
k2_recurrence(const float* __restrict__ W2, const float* __restrict__ b2)
{
    __shared__ __align__(16) float st[2][2][ST_SZ];   // [chain][buf][*]
    const int tid   = threadIdx.x;
    const int chain = tid >> 8;
    const int j     = (tid & 255) >> 1;   // output column 0..127
    const int h     = tid & 1;            // k-half 0/1
    const int b     = blockIdx.x * 2 + chain;

    // W2 half-column: pairs p_global = h*32 + p, p = 0..31
    ull w[32];
    #pragma unroll
    for (int p = 0; p < 32; p++) {
        int k = 2 * (h * 32 + p);
        w[p] = pk2(__ldg(W2 + (size_t)k     * 128 + j),
                   __ldg(W2 + (size_t)(k+1) * 128 + j));
    }
    const float b2v = __ldg(b2 + j);

    // zero both state buffers (write-once per thread pair; h==0 lane writes)
    if (h == 0) {
        int idx = (j < 64) ? j : j + ST_PAD;
        st[chain][0][idx] = 0.0f;
        st[chain][1][idx] = 0.0f;
    }
    __syncthreads();

    const float* Hp = g_H + (size_t)b * (T_*128) + j;
    float*       Fp = g_F + (size_t)b * (T_*128) + j;

    // prefetch ring (2 deep)
    float h0 = Hp[0];
    float h1 = Hp[128];

    const int half_off = h ? (64 + ST_PAD) : 0;   // float offset of my k-half

    int buf = 0;
    #pragma unroll 1
    for (int t = 0; t < T_; t += 2) {
        #pragma unroll
        for (int u = 0; u < 2; u++) {
            float hv = u ? h1 : h0;
            int tp = t + u + 2;
            float hn = 0.0f;
            if (tp < T_) hn = Hp[(size_t)tp * 128];
            if (u) h1 = hn; else h0 = hn;

            const ulonglong2* sp =
                (const ulonglong2*)(st[chain][buf] + half_off);
            ull a0 = 0ULL, a1 = 0ULL, a2 = 0ULL, a3 = 0ULL;
            #pragma unroll
            for (int q = 0; q < 8; q++) {
                ulonglong2 s01 = sp[2*q];       // pairs 4q, 4q+1 (local)
                ulonglong2 s23 = sp[2*q+1];     // pairs 4q+2, 4q+3
                a0 = ffma2(s01.x, w[4*q+0], a0);
                a1 = ffma2(s01.y, w[4*q+1], a1);
                a2 = ffma2(s23.x, w[4*q+2], a2);
                a3 = ffma2(s23.y, w[4*q+3], a3);
            }
            float x0,y0,x1,y1,x2,y2,x3,y3;
            upk2(a0,x0,y0); upk2(a1,x1,y1); upk2(a2,x2,y2); upk2(a3,x3,y3);
            float part = ((x0+y0)+(x1+y1)) + ((x2+y2)+(x3+y3));
            // combine the two k-halves: partner is lane^1 (same column j)
            part += __shfl_xor_sync(0xffffffffu, part, 1);

            float yv = hv + tanh_fast(part + b2v);
            if (h == 0) {
                int idx = (j < 64) ? j : j + ST_PAD;
                st[chain][buf^1][idx] = yv;
                Fp[(size_t)(t+u) * 128] = yv;
            }
            // per-chain barrier: 256 threads of this chain
            asm volatile("bar.sync %0, 256;" :: "r"(chain + 1) : "memory");
            buf ^= 1;
        }
    }
}

// ---------------------------------------------------------------------------
// K3: OUT = F @ Wc + bc. Tile 128x64, 256 thr, micro 8x4 (R2 version).
// ---------------------------------------------------------------------------
__global__ void __launch_bounds__(256, 2)
k3_head(const float* __restrict__ Wc, const float* __restrict__ bc,
        float* __restrict__ out)
{
    extern __shared__ float smem[];
    float2* Wp = (float2*)smem;        // [64][64] float2  (32 KB)
    float*  Xs = smem + 8192;          // [128][128] float (64 KB)
    const int tid = threadIdx.x;
    const int m0 = blockIdx.x * 128;

    {
        const int c4  = (tid & 15) * 4;
        const int kp0 = tid >> 4;
        #pragma unroll
        for (int pass = 0; pass < 4; pass++) {
            int kp = kp0 + pass * 16;
            float4 a = *(const float4*)(Wc + (size_t)(2*kp)   * 64 + c4);
            float4 b = *(const float4*)(Wc + (size_t)(2*kp+1) * 64 + c4);
            float2* w = Wp + kp*64 + c4;
            w[0] = make_float2(a.x, b.x);
            w[1] = make_float2(a.y, b.y);
            w[2] = make_float2(a.z, b.z);
            w[3] = make_float2(a.w, b.w);
        }
    }
    {
        const int q  = (tid & 31) * 4;
        const int r0 = tid >> 5;
        #pragma unroll
        for (int pass = 0; pass < 16; pass++) {
            int row = r0 + pass * 8;
            *(float4*)(Xs + row*128 + q) =
                *(const float4*)(g_F + (size_t)(m0+row)*128 + q);
        }
    }
    __syncthreads();

    const int tc = tid & 15;
    const int tr = tid >> 4;
    ull acc[8][4];
    #pragma unroll
    for (int i = 0; i < 8; i++)
        #pragma unroll
        for (int c = 0; c < 4; c++) acc[i][c] = 0ULL;

    const float*  xbase = Xs + tr * 8 * 128;
    const float2* wbase = Wp + tc * 4;

    #pragma unroll 8
    for (int kp = 0; kp < 64; kp++) {
        ulonglong2 wv0 = *(const ulonglong2*)(wbase + (size_t)kp*64);
        ulonglong2 wv1 = *(const ulonglong2*)(wbase + (size_t)kp*64 + 2);
        #pragma unroll
        for (int i = 0; i < 8; i++) {
            ull xp = *(const ull*)(xbase + i*128 + 2*kp);
            acc[i][0] = ffma2(xp, wv0.x, acc[i][0]);
            acc[i][1] = ffma2(xp, wv0.y, acc[i][1]);
            acc[i][2] = ffma2(xp, wv1.x, acc[i][2]);
            acc[i][3] = ffma2(xp, wv1.y, acc[i][3]);
        }
    }

    float bb[4];
    #pragma unroll
    for (int c = 0; c < 4; c++) bb[c] = __ldg(bc + tc*4 + c);

    #pragma unroll
    for (int i = 0; i < 8; i++) {
        int row = m0 + tr*8 + i;
        float4 o; float x, y;
        upk2(acc[i][0], x, y); o.x = x + y + bb[0];
        upk2(acc[i][1], x, y); o.y = x + y + bb[1];
        upk2(acc[i][2], x, y); o.z = x + y + bb[2];
        upk2(acc[i][3], x, y); o.w = x + y + bb[3];
        *(float4*)(out + (size_t)row*64 + tc*4) = o;
    }
}

extern "C" void kernel_launch(void* const* d_in, const int* in_sizes, int n_in,
                              void* d_out, int out_size) {
    (void)in_sizes; (void)n_in; (void)out_size;
    const float* X  = (const float*)d_in[0];
    const float* W1 = (const float*)d_in[1];
    const float* b1 = (const float*)d_in[2];
    const float* W2 = (const float*)d_in[3];
    const float* b2 = (const float*)d_in[4];
    const float* Wc = (const float*)d_in[5];
    const float* bc = (const float*)d_in[6];
    float* out = (float*)d_out;

    cudaFuncSetAttribute(k1_in_gemm, cudaFuncAttributeMaxDynamicSharedMemorySize, 98304);
    cudaFuncSetAttribute(k3_head,    cudaFuncAttributeMaxDynamicSharedMemorySize, 98304);

    k1_in_gemm<<<M_/64, 256, 98304>>>(X, W1, b1);
    k2_recurrence<<<B_/2, 512>>>(W2, b2);
    k3_head<<<M_/128, 256, 98304>>>(Wc, bc, out);
}